// round 12
// baseline (speedup 1.0000x reference)
#include <cuda_runtime.h>
#include <cuda_bf16.h>
#include <math.h>
#include <stdint.h>

#define NB 64
#define NN 512
#define GRID 148
#define NWARP (GRID * 8)            // 1184
#define NSTG 4
#define STG_BYTES 6144              // 3 tensors x 2KB
#define SMEM_DATA_OFF 1024
#define SMEM_TOTAL (SMEM_DATA_OFF + 8 * NSTG * STG_BYTES)   // 197632
#define LN2 0.6931471805599453

// Scratch (__device__ globals; zeroed at load; re-zeroed by the last block)
__device__ double g_pair[NB][8];    // [2]=dot [3]=na2 [4]=aSum [5]=ent(log2) [6]=con
__device__ double g_tot[8];         // 0=edge(log2) 1=sim 2=mse 3=smooth
__device__ int    g_done;

// ---------------------------------------------------------------------------
__device__ __forceinline__ uint32_t smem_u32(const void* p) {
    uint32_t a;
    asm("{ .reg .u64 t; cvta.to.shared.u64 t, %1; cvt.u32.u64 %0, t; }"
        : "=r"(a) : "l"(p));
    return a;
}
__device__ __forceinline__ void mbar_init(uint32_t bar, uint32_t cnt_) {
    asm volatile("mbarrier.init.shared.b64 [%0], %1;" :: "r"(bar), "r"(cnt_) : "memory");
}
__device__ __forceinline__ void fence_proxy_async_s() {
    asm volatile("fence.proxy.async.shared::cta;" ::: "memory");
}
__device__ __forceinline__ void mbar_expect_tx(uint32_t bar, uint32_t bytes) {
    asm volatile("mbarrier.arrive.expect_tx.shared.b64 _, [%0], %1;"
                 :: "r"(bar), "r"(bytes) : "memory");
}
__device__ __forceinline__ void bulk_g2s(uint32_t dst, const float* src,
                                         uint32_t bytes, uint32_t bar) {
    asm volatile("cp.async.bulk.shared::cta.global.mbarrier::complete_tx::bytes "
                 "[%0], [%1], %2, [%3];"
                 :: "r"(dst), "l"(src), "r"(bytes), "r"(bar) : "memory");
}
__device__ __forceinline__ void mbar_wait(uint32_t bar, uint32_t parity) {
    asm volatile(
        "{\n\t.reg .pred P;\n\t"
        "W_%=:\n\t"
        "mbarrier.try_wait.parity.acquire.cta.shared::cta.b64 P, [%0], %1, 0x989680;\n\t"
        "@P bra D_%=;\n\t"
        "bra W_%=;\n\t"
        "D_%=:\n\t}"
        :: "r"(bar), "r"(parity) : "memory");
}

// ---------------------------------------------------------------------------
// lean per-element: edge products + sim. a in {0,1}; vb = element valid.
__device__ __forceinline__ void lean_e(float p, float a, float s, bool vb,
                                       float& Px, float& Py, float& sim) {
    float w  = fmaf(-2.0f, p, 1.0f);
    float x0 = fmaf(a, w, p);
    float x  = vb ? x0 : 1.0f;
    float y  = vb ? 1.0f - x0 : 1.0f;
    float d  = vb ? s - a : 0.0f;
    Px *= x;
    Py *= y;
    sim = fmaf(d, d, sim);
}

// ---------------------------------------------------------------------------
__global__ void fused_kernel(
        const float* __restrict__ pc,      const float* __restrict__ adjm,
        const float* __restrict__ ncounts, const float* __restrict__ rsim,
        const float* __restrict__ temp,    const float* __restrict__ resw,
        const float* __restrict__ pts,     const float* __restrict__ adj,
        const void*  mask_raw,             float* __restrict__ out) {
    extern __shared__ char dsm[];
    const int tid  = threadIdx.x;
    const int lane = tid & 31;
    const int w    = tid >> 5;
    const unsigned full = 0xffffffffu;

    __shared__ int s_cnt[NB];
    __shared__ int s_pb[NB + 1];     // prefix over big-batch (cnt>50) rows
    __shared__ int s_ps[NB + 1];     // prefix over small-batch rows

    const uint32_t sbase    = smem_u32(dsm);
    const uint32_t bar_base = sbase + (uint32_t)w * NSTG * 8;
    const uint32_t dat_base = sbase + SMEM_DATA_OFF + (uint32_t)w * NSTG * STG_BYTES;

    // ---- mbarrier init (each warp owns its own ring) ----
    if (lane == 0) {
        #pragma unroll
        for (int s = 0; s < NSTG; ++s) mbar_init(bar_base + s * 8, 1);
    }
    fence_proxy_async_s();

    // ---- all 64 mask counts (warp w: batches 8w..8w+7), 2 ballot rounds ----
    {
        const unsigned char* mb = (const unsigned char*)mask_raw;
        unsigned char c0 = mb[0], c1 = mb[1];   // elem (0,0) is always true
        int mode = (c1 != 0) ? 0 : ((c0 != 0) ? 1 : 2);
        auto rd = [&](int idx) -> bool {
            if (mode == 0)      return mb[idx] != 0;
            else if (mode == 1) return ((const int*)mask_raw)[idx] != 0;
            else                return ((const float*)mask_raw)[idx] != 0.0f;
        };
        bool on1[8];
        #pragma unroll
        for (int q = 0; q < 8; ++q)
            on1[q] = rd((w * 8 + q) * NN + lane * 16 + 15);
        int kk[8];
        #pragma unroll
        for (int q = 0; q < 8; ++q)
            kk[q] = __popc(__ballot_sync(full, on1[q]));
        bool on2[8];
        #pragma unroll
        for (int q = 0; q < 8; ++q)
            on2[q] = (kk[q] < 32 && lane < 16)
                   ? rd((w * 8 + q) * NN + 16 * kk[q] + lane) : false;
        #pragma unroll
        for (int q = 0; q < 8; ++q) {
            unsigned bal = __ballot_sync(full, on2[q]);
            int c = (kk[q] == 32) ? NN : 16 * kk[q] + __popc(bal & 0xFFFFu);
            if (lane == 0) s_cnt[w * 8 + q] = c;
        }
    }
    __syncthreads();

    // ---- two prefix sums (warp 0): big rows / small rows ----
    if (w < 2) {
        int* dst = (w == 0) ? s_pb : s_ps;
        int c0 = s_cnt[lane], c1 = s_cnt[lane + 32];
        int v0 = (w == 0) ? (c0 > 50 ? c0 : 0) : (c0 > 50 ? 0 : c0);
        int v1 = (w == 0) ? (c1 > 50 ? c1 : 0) : (c1 > 50 ? 0 : c1);
        int a0 = v0;
        #pragma unroll
        for (int o = 1; o < 32; o <<= 1) {
            int t = __shfl_up_sync(full, a0, o);
            if (lane >= o) a0 += t;
        }
        int tot0 = __shfl_sync(full, a0, 31);
        int a1 = v1;
        #pragma unroll
        for (int o = 1; o < 32; o <<= 1) {
            int t = __shfl_up_sync(full, a1, o);
            if (lane >= o) a1 += t;
        }
        a1 += tot0;
        dst[lane + 1]  = a0;
        dst[lane + 33] = a1;
        if (lane == 0) dst[0] = 0;
    }
    __syncthreads();
    const int Rbig   = s_pb[NB];
    const int Rsmall = s_ps[NB];

    double accE = 0.0, accS = 0.0, accM = 0.0, accSm = 0.0;
    const int gw = blockIdx.x * 8 + w;

    // =================== PHASE A: TMA-pipelined big rows ===================
    {
        const int tmax = (gw < Rbig) ? (Rbig - gw + NWARP - 1) / NWARP : 0;

        auto map_row = [&](int t, int& b_, int& i_, int& cnt_) {
            int u = gw + t * NWARP;
            int lo = 0, hi = NB;
            #pragma unroll
            for (int it = 0; it < 6; ++it) {
                int mid = (lo + hi) >> 1;
                if (s_pb[mid] <= u) lo = mid; else hi = mid;
            }
            b_ = lo; i_ = u - s_pb[lo]; cnt_ = s_cnt[lo];
        };
        auto issue_row = [&](int t) {
            int b, i, cnt;
            map_row(t, b, i, cnt);
            uint32_t bytes = (uint32_t)((4 * cnt + 15) & ~15);
            const float* src = adjm + ((size_t)b * NN + i) * NN;
            const float* srcA = adj  + ((size_t)b * NN + i) * NN;
            const float* srcS = rsim + ((size_t)b * NN + i) * NN;
            int st = t & (NSTG - 1);
            uint32_t bar = bar_base + st * 8;
            uint32_t dst = dat_base + st * STG_BYTES;
            if (lane == 0) {
                mbar_expect_tx(bar, 3 * bytes);
                bulk_g2s(dst,        src,  bytes, bar);
                bulk_g2s(dst + 2048, srcA, bytes, bar);
                bulk_g2s(dst + 4096, srcS, bytes, bar);
            }
        };

        // prologue: fill the ring
        const int pro = (tmax < NSTG) ? tmax : NSTG;
        for (int t = 0; t < pro; ++t) issue_row(t);

        for (int t = 0; t < tmax; ++t) {
            const int st = t & (NSTG - 1);
            mbar_wait(bar_base + st * 8, (t >> 2) & 1);

            int b, i, cnt;
            map_row(t, b, i, cnt);
            const float* pp = (const float*)(dsm + SMEM_DATA_OFF
                              + (size_t)w * NSTG * STG_BYTES + (size_t)st * STG_BYTES);
            const float* aa = pp + 512;
            const float* ss = pp + 1024;
            const float4* p4 = (const float4*)pp;
            const float4* a4 = (const float4*)aa;
            const float4* s4 = (const float4*)ss;
            const int cnt4 = (cnt + 3) >> 2;
            const int m1 = cnt4 - 1;
            const int ca = lane,      cb = lane + 32;
            const int cc = lane + 64, cd = lane + 96;
            const int ka = min(ca, m1), kb = min(cb, m1);
            const int kc = min(cc, m1), kd = min(cd, m1);
            float4 P0 = p4[ka], P1 = p4[kb], P2 = p4[kc], P3 = p4[kd];
            float4 A0 = a4[ka], A1 = a4[kb], A2 = a4[kc], A3 = a4[kd];
            float4 S0 = s4[ka], S1 = s4[kb], S2 = s4[kc], S3 = s4[kd];
            float Px = 1.f, Py = 1.f, sim = 0.f;
            #define DOSLOT(P4_,A4_,S4_,JB) do {                              \
                lean_e(P4_.x, A4_.x, S4_.x, (JB)+0 < cnt, Px, Py, sim);      \
                lean_e(P4_.y, A4_.y, S4_.y, (JB)+1 < cnt, Px, Py, sim);      \
                lean_e(P4_.z, A4_.z, S4_.z, (JB)+2 < cnt, Px, Py, sim);      \
                lean_e(P4_.w, A4_.w, S4_.w, (JB)+3 < cnt, Px, Py, sim); } while(0)
            DOSLOT(P0, A0, S0, 4 * ca);
            DOSLOT(P1, A1, S1, 4 * cb);
            DOSLOT(P2, A2, S2, 4 * cc);
            DOSLOT(P3, A3, S3, 4 * cd);
            #undef DOSLOT
            accE += (double)fmaf(0.05f, __log2f(Px), 0.95f * __log2f(Py));
            accS += (double)sim;

            __syncwarp();                      // all lanes done reading stage
            if (t + NSTG < tmax) issue_row(t + NSTG);
        }
    }

    // ============ PHASE B: small rows + coord units (direct LDG) ===========
    for (int u = gw; u < Rsmall + NB; u += NWARP) {
        if (u < Rsmall) {
            int lo = 0, hi = NB;
            #pragma unroll
            for (int it = 0; it < 6; ++it) {
                int mid = (lo + hi) >> 1;
                if (s_ps[mid] <= u) lo = mid; else hi = mid;
            }
            const int b   = lo;
            const int i   = u - s_ps[lo];
            const int cnt = s_cnt[b];
            const size_t rb = ((size_t)b * NN + i) * NN;
            const int j0 = lane, j1 = lane + 32;
            const int mm = cnt - 1;
            const int k0 = min(j0, mm), k1 = min(j1, mm);
            float p0 = __ldg(adjm + rb + k0);
            float p1 = __ldg(adjm + rb + k1);
            float a0 = __ldg(adj  + rb + k0);
            float a1 = __ldg(adj  + rb + k1);
            float s0 = __ldg(rsim + rb + k0);
            float s1 = __ldg(rsim + rb + k1);
            const bool i0 = j0 >= cnt, i1 = j1 >= cnt;
            p0 = i0 ? 0.5f : p0;  a0 = i0 ? 0.f : a0;  s0 = i0 ? 0.f : s0;
            p1 = i1 ? 0.5f : p1;  a1 = i1 ? 0.f : a1;  s1 = i1 ? 0.f : s1;
            float sL=0,sM=0,sAt=0,sSim=0,sDot=0,sP2=0,sA=0,sPt=0,sCon=0;
            #pragma unroll
            for (int e = 0; e < 2; ++e) {
                float p = e ? p1 : p0, a = e ? a1 : a0, s = e ? s1 : s0;
                float L = __log2f(p), M = __log2f(1.0f - p);
                float t = L - M;
                sL += L; sM += M;
                sAt = fmaf(a, t, sAt);
                float ds = s - a;
                sSim = fmaf(ds, ds, sSim);
                sDot = fmaf(p, a, sDot);
                sP2  = fmaf(p, p, sP2);
                sA  += a;
                sPt  = fmaf(p, t, sPt);
                sCon += fabsf(p - 0.5f);
            }
            float inv = (i0 ? 1.f : 0.f) + (i1 ? 1.f : 0.f);
            sL += inv; sM += inv; sP2 -= 0.25f * inv;
            accE += (double)fmaf(0.05f, sL, fmaf(0.95f, sM, 0.9f * sAt));
            accS += (double)sSim;
            float v5[5] = {sDot, sP2, sA, sM + sPt, sCon};
            #pragma unroll
            for (int k = 0; k < 5; ++k)
                #pragma unroll
                for (int o = 16; o; o >>= 1)
                    v5[k] += __shfl_down_sync(full, v5[k], o);
            if (lane == 0) {
                atomicAdd(&g_pair[b][2], (double)v5[0]);
                atomicAdd(&g_pair[b][3], (double)v5[1]);
                atomicAdd(&g_pair[b][4], (double)v5[2]);
                atomicAdd(&g_pair[b][5], (double)v5[3]);
                atomicAdd(&g_pair[b][6], (double)v5[4]);
            }
        } else {
            const int b   = u - Rsmall;
            const int cnt = s_cnt[b];
            const float2* pc2  = (const float2*)pc + (size_t)b * NN;
            const float2* pts2 = (const float2*)pts + (size_t)b * NN;
            const int mm = cnt - 1;
            float mse = 0.f, smo = 0.f;
            for (int n0 = lane; n0 < cnt; n0 += 128) {
                const int n1 = n0 + 32, n2 = n0 + 64, n3 = n0 + 96;
                const int q1 = min(n1, mm);
                const int q2 = min(n2, mm), q3 = min(n3, mm);
                float2 u0 = __ldg(pc2 + n0);
                float2 u1 = __ldg(pc2 + q1);
                float2 u2 = __ldg(pc2 + q2);
                float2 u3 = __ldg(pc2 + q3);
                float2 v0 = __ldg(pts2 + n0);
                float2 v1 = __ldg(pts2 + q1);
                float2 v2 = __ldg(pts2 + q2);
                float2 v3 = __ldg(pts2 + q3);
                #define COORD1(UU,VV,NI) do {                                 \
                    bool vz = (NI) < cnt;                                     \
                    float dx = vz ? (UU.x - VV.x) : 0.f;                      \
                    float dy = vz ? (UU.y - VV.y) : 0.f;                      \
                    mse += dx * dx + dy * dy;                                 \
                    float ax = fabsf(dx), ay = fabsf(dy);                     \
                    smo += (ax < 1.0f ? 0.5f * dx * dx : ax - 0.5f)           \
                         + (ay < 1.0f ? 0.5f * dy * dy : ay - 0.5f); } while(0)
                COORD1(u0, v0, n0);
                COORD1(u1, v1, n1);
                COORD1(u2, v2, n2);
                COORD1(u3, v3, n3);
                #undef COORD1
            }
            accM  += (double)mse;
            accSm += (double)smo;
        }
    }

    // ---- single block-reduce of the 4 global accumulators ----
    {
        __shared__ double sh[8][4];
        double v[4] = {accE, accS, accM, accSm};
        #pragma unroll
        for (int k = 0; k < 4; ++k) {
            #pragma unroll
            for (int o = 16; o; o >>= 1) v[k] += __shfl_down_sync(full, v[k], o);
            if (lane == 0) sh[w][k] = v[k];
        }
        __syncthreads();
        if (w == 0 && lane < 4) {
            double xx = 0.0;
            #pragma unroll
            for (int ww = 0; ww < 8; ++ww) xx += sh[ww][lane];
            atomicAdd(&g_tot[lane], xx);
        }
    }

    // ---- completion counter: last block finalizes ----
    __shared__ int s_last;
    __threadfence();
    __syncthreads();
    if (tid == 0) {
        int done = atomicAdd(&g_done, 1);
        s_last = (done == GRID - 1) ? 1 : 0;
    }
    __syncthreads();
    if (!s_last) return;
    __threadfence();

    // ---- finalize (thread t<NB handles batch t) ----
    double c2 = 0.0, cntd = 0.0, cl = 0.0, ac = 0.0;
    if (tid < NB) {
        int ci = s_cnt[tid];
        cntd   = (double)ci;
        c2     = cntd * cntd;
        double dc  = (double)__ldg(ncounts + tid) - cntd;
        double adc = fabs(dc);
        cl = (adc <= 1.0) ? 0.5 * dc * dc : adc - 0.5;
        if (ci > 5 && ci <= 50) {
            double dot  = g_pair[tid][2];
            double na2  = g_pair[tid][3];
            double nt2  = g_pair[tid][4];
            double entn = g_pair[tid][5] * LN2;
            double con  = g_pair[tid][6];
            double na   = sqrt(na2), nt = sqrt(nt2);
            double cosv = dot / (fmax(na, 1e-8) * fmax(nt, 1e-8));
            double n2   = fmax(c2, 1.0);
            ac = (-cosv - 0.2 * (con / n2)) + 0.1 * (-entn / n2);
        }
    }
    {
        __shared__ double sh2[8][4];
        double v[4] = {c2, cntd, cl, ac};
        #pragma unroll
        for (int k = 0; k < 4; ++k) {
            #pragma unroll
            for (int o = 16; o; o >>= 1) v[k] += __shfl_down_sync(full, v[k], o);
            if (lane == 0) sh2[w][k] = v[k];
        }
        __syncthreads();
        if (tid == 0) {
            double t4[4];
            #pragma unroll
            for (int k = 0; k < 4; ++k) {
                double xx = 0.0;
                #pragma unroll
                for (int ww = 0; ww < 8; ++ww) xx += sh2[ww][k];
                t4[k] = xx;
            }
            double cnt2       = fmax(t4[0], 1.0);
            double cnt_coord  = fmax(t4[1] * 2.0, 1.0);
            double edge_loss  = -(g_tot[0] * LN2) / cnt2;
            double sim_loss   = g_tot[1] / cnt2;
            double coord_loss = 0.7 * (g_tot[2] / cnt_coord)
                              + 0.3 * (g_tot[3] / cnt_coord);
            double count_loss = t4[2] / (double)NB;
            double temp_reg   = fabs((double)__ldg(temp) - 1.0);
            double res_reg    = fabs((double)__ldg(resw) - 0.5);
            double total = coord_loss + 2.0 * edge_loss + 0.1 * count_loss
                         + 0.3 * sim_loss + 0.01 * (temp_reg + res_reg) + t4[3];
            out[0] = (float)total;
        }
    }
    __syncthreads();

    // ---- reset scratch for the next graph replay ----
    for (int k = tid; k < NB * 8; k += 256)
        ((double*)g_pair)[k] = 0.0;
    if (tid < 8) g_tot[tid] = 0.0;
    if (tid == 0) g_done = 0;
}

// ---------------------------------------------------------------------------
extern "C" void kernel_launch(void* const* d_in, const int* in_sizes, int n_in,
                              void* d_out, int out_size) {
    const float* pc      = (const float*)d_in[0];
    const float* adjm    = (const float*)d_in[1];
    const float* ncounts = (const float*)d_in[2];
    const float* rsim    = (const float*)d_in[3];
    const float* temp    = (const float*)d_in[4];
    const float* resw    = (const float*)d_in[5];
    const float* pts     = (const float*)d_in[6];
    const float* adj     = (const float*)d_in[7];
    const void*  mask    = d_in[8];

    cudaFuncSetAttribute(fused_kernel,
                         cudaFuncAttributeMaxDynamicSharedMemorySize, SMEM_TOTAL);
    fused_kernel<<<GRID, 256, SMEM_TOTAL>>>(pc, adjm, ncounts, rsim, temp,
                                            resw, pts, adj, mask,
                                            (float*)d_out);
    (void)in_sizes; (void)n_in; (void)out_size;
}

// round 13
// speedup vs baseline: 1.1831x; 1.1831x over previous
#include <cuda_runtime.h>
#include <cuda_bf16.h>
#include <math.h>

#define NB 64
#define NN 512
#define GRID 296
#define NWARP (GRID * 8)            // 2368
#define LN2 0.6931471805599453

// Scratch (__device__ globals; zeroed at load; re-zeroed by the last block)
__device__ double g_pair[NB][8];    // [2]=dot [3]=na2 [4]=aSum [5]=ent(log2) [6]=con
__device__ double g_tot[8];         // 0=edge(log2) 1=sim 2=mse 3=smooth
__device__ int    g_done;

// ---------------------------------------------------------------------------
// masked element op (last strip only): identity when !vb
__device__ __forceinline__ void lean_m(float p, float a, float s, bool vb,
                                       float& Px, float& Py, float& sim) {
    float w  = fmaf(-2.0f, p, 1.0f);
    float x0 = fmaf(a, w, p);
    float x  = vb ? x0 : 1.0f;
    float y  = vb ? 1.0f - x0 : 1.0f;
    float d  = vb ? s - a : 0.0f;
    Px *= x;
    Py *= y;
    sim = fmaf(d, d, sim);
}
// unmasked element op (strips known fully valid): 7 instrs
__device__ __forceinline__ void lean_u(float p, float a, float s,
                                       float& Px, float& Py, float& sim) {
    float x = fmaf(a, fmaf(-2.0f, p, 1.0f), p);
    Px *= x;
    Py *= 1.0f - x;
    float d = s - a;
    sim = fmaf(d, d, sim);
}

// ---------------------------------------------------------------------------
// One lean row with NS strips (NS = ceil(cnt4/32), 1..4).
// Strips 0..NS-2: cols lane+32k <= cnt4-2 -> fully valid, unmasked.
// Strip NS-1: clamped col, per-element mask.
template<int NS>
__device__ __forceinline__ void lean_row(
        const float4* __restrict__ pr, const float4* __restrict__ ar,
        const float4* __restrict__ sr, int lane, int cnt, int cnt4,
        double& accE, double& accS) {
    float Px = 1.f, Py = 1.f, sim = 0.f;
    const int cl = lane + 32 * (NS - 1);        // last-strip col4
    const int kl = min(cl, cnt4 - 1);
    // ---- batched loads: 3*NS back-to-back LDG.128 ----
    float4 P[NS], A[NS], S[NS];
    #pragma unroll
    for (int k = 0; k < NS - 1; ++k) P[k] = __ldg(pr + lane + 32 * k);
    P[NS - 1] = __ldg(pr + kl);
    #pragma unroll
    for (int k = 0; k < NS - 1; ++k) A[k] = __ldg(ar + lane + 32 * k);
    A[NS - 1] = __ldg(ar + kl);
    #pragma unroll
    for (int k = 0; k < NS - 1; ++k) S[k] = __ldg(sr + lane + 32 * k);
    S[NS - 1] = __ldg(sr + kl);
    // ---- math: unmasked strips ----
    #pragma unroll
    for (int k = 0; k < NS - 1; ++k) {
        lean_u(P[k].x, A[k].x, S[k].x, Px, Py, sim);
        lean_u(P[k].y, A[k].y, S[k].y, Px, Py, sim);
        lean_u(P[k].z, A[k].z, S[k].z, Px, Py, sim);
        lean_u(P[k].w, A[k].w, S[k].w, Px, Py, sim);
    }
    // ---- masked last strip (validity from ORIGINAL col cl) ----
    lean_m(P[NS-1].x, A[NS-1].x, S[NS-1].x, 4 * cl + 0 < cnt, Px, Py, sim);
    lean_m(P[NS-1].y, A[NS-1].y, S[NS-1].y, 4 * cl + 1 < cnt, Px, Py, sim);
    lean_m(P[NS-1].z, A[NS-1].z, S[NS-1].z, 4 * cl + 2 < cnt, Px, Py, sim);
    lean_m(P[NS-1].w, A[NS-1].w, S[NS-1].w, 4 * cl + 3 < cnt, Px, Py, sim);
    // 2 MUFU per row (<=16 elems/lane; min 0.02^16 ~ 6e-28: normal)
    accE += (double)fmaf(0.05f, __log2f(Px), 0.95f * __log2f(Py));
    accS += (double)sim;
}

// ---------------------------------------------------------------------------
__global__ __launch_bounds__(256, 2) void fused_kernel(
        const float* __restrict__ pc,      const float* __restrict__ adjm,
        const float* __restrict__ ncounts, const float* __restrict__ rsim,
        const float* __restrict__ temp,    const float* __restrict__ resw,
        const float* __restrict__ pts,     const float* __restrict__ adj,
        const void*  mask_raw,             float* __restrict__ out) {
    const int tid  = threadIdx.x;
    const int lane = tid & 31;
    const int w    = tid >> 5;
    const unsigned full = 0xffffffffu;

    __shared__ int s_cnt[NB];
    __shared__ int s_pref[NB + 1];

    // ---- all 64 mask counts (warp w: batches 8w..8w+7), 2 ballot rounds ----
    {
        const unsigned char* mb = (const unsigned char*)mask_raw;
        unsigned char c0 = mb[0], c1 = mb[1];   // elem (0,0) is always true
        int mode = (c1 != 0) ? 0 : ((c0 != 0) ? 1 : 2);
        auto rd = [&](int idx) -> bool {
            if (mode == 0)      return mb[idx] != 0;
            else if (mode == 1) return ((const int*)mask_raw)[idx] != 0;
            else                return ((const float*)mask_raw)[idx] != 0.0f;
        };
        bool on1[8];
        #pragma unroll
        for (int q = 0; q < 8; ++q)
            on1[q] = rd((w * 8 + q) * NN + lane * 16 + 15);
        int kk[8];
        #pragma unroll
        for (int q = 0; q < 8; ++q)
            kk[q] = __popc(__ballot_sync(full, on1[q]));
        bool on2[8];
        #pragma unroll
        for (int q = 0; q < 8; ++q)
            on2[q] = (kk[q] < 32 && lane < 16)
                   ? rd((w * 8 + q) * NN + 16 * kk[q] + lane) : false;
        #pragma unroll
        for (int q = 0; q < 8; ++q) {
            unsigned bal = __ballot_sync(full, on2[q]);
            int c = (kk[q] == 32) ? NN : 16 * kk[q] + __popc(bal & 0xFFFFu);
            if (lane == 0) s_cnt[w * 8 + q] = c;
        }
    }
    __syncthreads();

    // ---- prefix sum over the 64 counts (warp 0) ----
    if (w == 0) {
        int v0 = s_cnt[lane], v1 = s_cnt[lane + 32];
        int a0 = v0;
        #pragma unroll
        for (int o = 1; o < 32; o <<= 1) {
            int t = __shfl_up_sync(full, a0, o);
            if (lane >= o) a0 += t;
        }
        int tot0 = __shfl_sync(full, a0, 31);
        int a1 = v1;
        #pragma unroll
        for (int o = 1; o < 32; o <<= 1) {
            int t = __shfl_up_sync(full, a1, o);
            if (lane >= o) a1 += t;
        }
        a1 += tot0;
        s_pref[lane + 1]  = a0;
        s_pref[lane + 33] = a1;
        if (lane == 0) s_pref[0] = 0;
    }
    __syncthreads();
    const int R = s_pref[NB];           // total valid rows (~10K)

    double accE = 0.0, accS = 0.0, accM = 0.0, accSm = 0.0;
    const int gw = blockIdx.x * 8 + w;

    for (int u = gw; u < R + NB; u += NWARP) {
        if (u < R) {
            // ---- map global row u -> (b, i) via binary search ----
            int lo = 0, hi = NB;
            #pragma unroll
            for (int it = 0; it < 6; ++it) {
                int mid = (lo + hi) >> 1;
                if (s_pref[mid] <= u) lo = mid; else hi = mid;
            }
            const int b   = lo;
            const int i   = u - s_pref[lo];
            const int cnt = s_cnt[b];
            const size_t rb = ((size_t)b * NN + i) * NN;

            if (cnt > 50) {
                const float4* pr = (const float4*)(adjm + rb);
                const float4* ar = (const float4*)(adj  + rb);
                const float4* sr = (const float4*)(rsim + rb);
                const int cnt4 = (cnt + 3) >> 2;
                const int ns = (cnt4 + 31) >> 5;   // 1..4 strips
                switch (ns) {
                    case 1: lean_row<1>(pr, ar, sr, lane, cnt, cnt4, accE, accS); break;
                    case 2: lean_row<2>(pr, ar, sr, lane, cnt, cnt4, accE, accS); break;
                    case 3: lean_row<3>(pr, ar, sr, lane, cnt, cnt4, accE, accS); break;
                    default: lean_row<4>(pr, ar, sr, lane, cnt, cnt4, accE, accS); break;
                }
            } else {
                // ---- FULL row (small batch, cnt<=50): 6 clamped loads ----
                const int j0 = lane, j1 = lane + 32;
                const int mm = cnt - 1;
                const int k0 = min(j0, mm), k1 = min(j1, mm);
                float p0 = __ldg(adjm + rb + k0);
                float p1 = __ldg(adjm + rb + k1);
                float a0 = __ldg(adj  + rb + k0);
                float a1 = __ldg(adj  + rb + k1);
                float s0 = __ldg(rsim + rb + k0);
                float s1 = __ldg(rsim + rb + k1);
                const bool i0 = j0 >= cnt, i1 = j1 >= cnt;
                p0 = i0 ? 0.5f : p0;  a0 = i0 ? 0.f : a0;  s0 = i0 ? 0.f : s0;
                p1 = i1 ? 0.5f : p1;  a1 = i1 ? 0.f : a1;  s1 = i1 ? 0.f : s1;
                float sL=0,sM=0,sAt=0,sSim=0,sDot=0,sP2=0,sA=0,sPt=0,sCon=0;
                #pragma unroll
                for (int e = 0; e < 2; ++e) {
                    float p = e ? p1 : p0, a = e ? a1 : a0, s = e ? s1 : s0;
                    float L = __log2f(p), M = __log2f(1.0f - p);
                    float t = L - M;
                    sL += L; sM += M;
                    sAt = fmaf(a, t, sAt);
                    float ds = s - a;
                    sSim = fmaf(ds, ds, sSim);
                    sDot = fmaf(p, a, sDot);
                    sP2  = fmaf(p, p, sP2);
                    sA  += a;
                    sPt  = fmaf(p, t, sPt);
                    sCon += fabsf(p - 0.5f);
                }
                // invalid elem contributed: L=-1, M=-1, p^2=0.25, rest 0
                float inv = (i0 ? 1.f : 0.f) + (i1 ? 1.f : 0.f);
                sL += inv; sM += inv; sP2 -= 0.25f * inv;
                accE += (double)fmaf(0.05f, sL, fmaf(0.95f, sM, 0.9f * sAt));
                accS += (double)sSim;
                float v5[5] = {sDot, sP2, sA, sM + sPt, sCon};
                #pragma unroll
                for (int k = 0; k < 5; ++k)
                    #pragma unroll
                    for (int o = 16; o; o >>= 1)
                        v5[k] += __shfl_down_sync(full, v5[k], o);
                if (lane == 0) {
                    atomicAdd(&g_pair[b][2], (double)v5[0]);
                    atomicAdd(&g_pair[b][3], (double)v5[1]);
                    atomicAdd(&g_pair[b][4], (double)v5[2]);
                    atomicAdd(&g_pair[b][5], (double)v5[3]);
                    atomicAdd(&g_pair[b][6], (double)v5[4]);
                }
            }
        } else {
            // ---- coord unit for batch b: 4-way unrolled clamped loads ----
            const int b   = u - R;
            const int cnt = s_cnt[b];
            const float2* pc2  = (const float2*)pc + (size_t)b * NN;
            const float2* pts2 = (const float2*)pts + (size_t)b * NN;
            const int mm = cnt - 1;
            float mse = 0.f, smo = 0.f;
            for (int n0 = lane; n0 < cnt; n0 += 128) {
                const int n1 = n0 + 32, n2 = n0 + 64, n3 = n0 + 96;
                const int q1 = min(n1, mm);
                const int q2 = min(n2, mm), q3 = min(n3, mm);
                float2 u0 = __ldg(pc2 + n0);
                float2 u1 = __ldg(pc2 + q1);
                float2 u2 = __ldg(pc2 + q2);
                float2 u3 = __ldg(pc2 + q3);
                float2 v0 = __ldg(pts2 + n0);
                float2 v1 = __ldg(pts2 + q1);
                float2 v2 = __ldg(pts2 + q2);
                float2 v3 = __ldg(pts2 + q3);
                #define COORD1(UU,VV,NI) do {                                 \
                    bool vz = (NI) < cnt;                                     \
                    float dx = vz ? (UU.x - VV.x) : 0.f;                      \
                    float dy = vz ? (UU.y - VV.y) : 0.f;                      \
                    mse += dx * dx + dy * dy;                                 \
                    float ax = fabsf(dx), ay = fabsf(dy);                     \
                    smo += (ax < 1.0f ? 0.5f * dx * dx : ax - 0.5f)           \
                         + (ay < 1.0f ? 0.5f * dy * dy : ay - 0.5f); } while(0)
                COORD1(u0, v0, n0);
                COORD1(u1, v1, n1);
                COORD1(u2, v2, n2);
                COORD1(u3, v3, n3);
                #undef COORD1
            }
            accM  += (double)mse;
            accSm += (double)smo;
        }
    }

    // ---- single block-reduce of the 4 global accumulators ----
    {
        __shared__ double sh[8][4];
        double v[4] = {accE, accS, accM, accSm};
        #pragma unroll
        for (int k = 0; k < 4; ++k) {
            #pragma unroll
            for (int o = 16; o; o >>= 1) v[k] += __shfl_down_sync(full, v[k], o);
            if (lane == 0) sh[w][k] = v[k];
        }
        __syncthreads();
        if (w == 0 && lane < 4) {
            double xx = 0.0;
            #pragma unroll
            for (int ww = 0; ww < 8; ++ww) xx += sh[ww][lane];
            atomicAdd(&g_tot[lane], xx);
        }
    }

    // ---- completion counter: last block finalizes ----
    __shared__ int s_last;
    __threadfence();
    __syncthreads();
    if (tid == 0) {
        int done = atomicAdd(&g_done, 1);
        s_last = (done == GRID - 1) ? 1 : 0;
    }
    __syncthreads();
    if (!s_last) return;
    __threadfence();

    // ---- finalize (thread t<NB handles batch t) ----
    double c2 = 0.0, cntd = 0.0, cl = 0.0, ac = 0.0;
    if (tid < NB) {
        int ci = s_cnt[tid];
        cntd   = (double)ci;
        c2     = cntd * cntd;
        double dc  = (double)__ldg(ncounts + tid) - cntd;
        double adc = fabs(dc);
        cl = (adc <= 1.0) ? 0.5 * dc * dc : adc - 0.5;
        if (ci > 5 && ci <= 50) {
            double dot  = g_pair[tid][2];
            double na2  = g_pair[tid][3];
            double nt2  = g_pair[tid][4];
            double entn = g_pair[tid][5] * LN2;
            double con  = g_pair[tid][6];
            double na   = sqrt(na2), nt = sqrt(nt2);
            double cosv = dot / (fmax(na, 1e-8) * fmax(nt, 1e-8));
            double n2   = fmax(c2, 1.0);
            ac = (-cosv - 0.2 * (con / n2)) + 0.1 * (-entn / n2);
        }
    }
    {
        __shared__ double sh2[8][4];
        double v[4] = {c2, cntd, cl, ac};
        #pragma unroll
        for (int k = 0; k < 4; ++k) {
            #pragma unroll
            for (int o = 16; o; o >>= 1) v[k] += __shfl_down_sync(full, v[k], o);
            if (lane == 0) sh2[w][k] = v[k];
        }
        __syncthreads();
        if (tid == 0) {
            double t4[4];
            #pragma unroll
            for (int k = 0; k < 4; ++k) {
                double xx = 0.0;
                #pragma unroll
                for (int ww = 0; ww < 8; ++ww) xx += sh2[ww][k];
                t4[k] = xx;
            }
            double cnt2       = fmax(t4[0], 1.0);
            double cnt_coord  = fmax(t4[1] * 2.0, 1.0);
            double edge_loss  = -(g_tot[0] * LN2) / cnt2;
            double sim_loss   = g_tot[1] / cnt2;
            double coord_loss = 0.7 * (g_tot[2] / cnt_coord)
                              + 0.3 * (g_tot[3] / cnt_coord);
            double count_loss = t4[2] / (double)NB;
            double temp_reg   = fabs((double)__ldg(temp) - 1.0);
            double res_reg    = fabs((double)__ldg(resw) - 0.5);
            double total = coord_loss + 2.0 * edge_loss + 0.1 * count_loss
                         + 0.3 * sim_loss + 0.01 * (temp_reg + res_reg) + t4[3];
            out[0] = (float)total;
        }
    }
    __syncthreads();

    // ---- reset scratch for the next graph replay ----
    for (int k = tid; k < NB * 8; k += 256)
        ((double*)g_pair)[k] = 0.0;
    if (tid < 8) g_tot[tid] = 0.0;
    if (tid == 0) g_done = 0;
}

// ---------------------------------------------------------------------------
extern "C" void kernel_launch(void* const* d_in, const int* in_sizes, int n_in,
                              void* d_out, int out_size) {
    const float* pc      = (const float*)d_in[0];
    const float* adjm    = (const float*)d_in[1];
    const float* ncounts = (const float*)d_in[2];
    const float* rsim    = (const float*)d_in[3];
    const float* temp    = (const float*)d_in[4];
    const float* resw    = (const float*)d_in[5];
    const float* pts     = (const float*)d_in[6];
    const float* adj     = (const float*)d_in[7];
    const void*  mask    = d_in[8];

    fused_kernel<<<GRID, 256>>>(pc, adjm, ncounts, rsim, temp, resw,
                                pts, adj, mask, (float*)d_out);
    (void)in_sizes; (void)n_in; (void)out_size;
}